// round 8
// baseline (speedup 1.0000x reference)
#include <cuda_runtime.h>
#include <cstdint>

#define B_ 2
#define H_ 8
#define S_ 1024
#define DK_ 64
#define DV_ 64
static constexpr float INV_T = 0.125f;                   // 1/temperature
static constexpr int OUT_ATTN_OFF = B_ * H_ * S_ * DV_;  // 1048576

// ---- packed fp32 helpers (sm_103a f32x2 pipe) -------------------------------
#define FMA2(acc, a, b) asm("fma.rn.f32x2 %0, %1, %2, %0;" : "+l"(acc) : "l"(a), "l"(b))

__device__ __forceinline__ unsigned long long pack2(float lo, float hi) {
    unsigned long long r;
    asm("mov.b64 %0, {%1, %2};" : "=l"(r) : "f"(lo), "f"(hi));
    return r;
}
__device__ __forceinline__ float2 unpack2(unsigned long long v) {
    float2 r;
    asm("mov.b64 {%0, %1}, %2;" : "=f"(r.x), "=f"(r.y) : "l"(v));
    return r;
}

// ---- cp.async helpers -------------------------------------------------------
__device__ __forceinline__ uint32_t s2u(const void* p) {
    return (uint32_t)__cvta_generic_to_shared(p);
}
__device__ __forceinline__ void cp8(uint32_t dst, const void* src) {
    asm volatile("cp.async.ca.shared.global [%0], [%1], 8;" :: "r"(dst), "l"(src));
}
__device__ __forceinline__ void cp16(uint32_t dst, const void* src) {
    asm volatile("cp.async.cg.shared.global [%0], [%1], 16;" :: "r"(dst), "l"(src));
}
#define CP_COMMIT() asm volatile("cp.async.commit_group;")
#define CP_WAIT1()  asm volatile("cp.async.wait_group 1;")
#define CP_WAIT0()  asm volatile("cp.async.wait_group 0;")

// ---------------------------------------------------------------------------
// K1 (REBUILT): attn1[b,h,i,j] = (q/T)[b,h,i,:] . k[b,h,j,:]
// d-parity packing: acc[(r,s)] += (q[i][2dp],q[i][2dp+1]) (*) (k[j][2dp],k[j][2dp+1])
// Natural [row][d] smem layout (pitch 66) -> NO transpose, NO dup2. cp8 staging.
// Tile 128i x 64j, 256 threads, 8x4 micro (j strided by 16: conflict-free LDS.64).
// ---------------------------------------------------------------------------
static constexpr int K1_PITCH = 66;
static constexpr int K1_SMEM = (128 + 64) * K1_PITCH * 4;   // 50688 B

__global__ void __launch_bounds__(256, 2) k1_qk(const float* __restrict__ q,
                                                const float* __restrict__ k,
                                                float* __restrict__ attn)
{
    extern __shared__ float sm1[];
    float* Qs = sm1;                    // [128][66]
    float* Ks = sm1 + 128 * K1_PITCH;   // [64][66]

    const int bh = blockIdx.z;
    const int i0 = blockIdx.y * 128;
    const int j0 = blockIdx.x * 64;
    const float* qb = q + ((size_t)bh * S_ + i0) * DK_;
    const float* kb = k + ((size_t)bh * S_ + j0) * DK_;
    const int t = threadIdx.x;
    const uint32_t qs_u = s2u(Qs), ks_u = s2u(Ks);

    // stage natural layout: row copies, 8B ops (dst 8B-aligned: row*264 + 8p)
    #pragma unroll
    for (int m = 0; m < 16; m++) {
        const int idx = m * 256 + t;
        const int row = idx >> 5, p = idx & 31;
        cp8(qs_u + (uint32_t)(row * K1_PITCH + 2 * p) * 4u, qb + (size_t)idx * 2);
    }
    #pragma unroll
    for (int m = 0; m < 8; m++) {
        const int idx = m * 256 + t;
        const int row = idx >> 5, p = idx & 31;
        cp8(ks_u + (uint32_t)(row * K1_PITCH + 2 * p) * 4u, kb + (size_t)idx * 2);
    }
    CP_COMMIT();
    CP_WAIT0();
    __syncthreads();

    const int tx = t & 15;   // j = tx + 16*s (strided: LDS banks 2*(tx+16s) distinct)
    const int ty = t >> 4;   // i = ty*8 + r
    const float* qp = Qs + (ty * 8) * K1_PITCH;
    const float* kp = Ks + tx * K1_PITCH;

    unsigned long long acc[8][4] = {};   // packed (even-d, odd-d) partials

    #pragma unroll 8
    for (int dp = 0; dp < 32; dp++) {
        unsigned long long kv[4], qv[8];
        #pragma unroll
        for (int s = 0; s < 4; s++)
            kv[s] = *(const unsigned long long*)(kp + (16 * s) * K1_PITCH + 2 * dp);
        #pragma unroll
        for (int r = 0; r < 8; r++)
            qv[r] = *(const unsigned long long*)(qp + r * K1_PITCH + 2 * dp);
        #pragma unroll
        for (int r = 0; r < 8; r++)
            #pragma unroll
            for (int s = 0; s < 4; s++)
                FMA2(acc[r][s], qv[r], kv[s]);
    }

    #pragma unroll
    for (int r = 0; r < 8; r++) {
        float* row = attn + (((size_t)bh * S_ + i0 + ty * 8 + r) * S_) + j0;
        #pragma unroll
        for (int s = 0; s < 4; s++) {
            float2 pv = unpack2(acc[r][s]);
            row[tx + 16 * s] = (pv.x + pv.y) * INV_T;   // h-sum + 1/T here
        }
    }
}

// ---------------------------------------------------------------------------
// K2 (REBUILT): per (b,i): logits[h][j] = attn1[h][j] + qs[h,:].rpr[b,i,j,:]
// d-parity packing: acc_h += (q[h][2dp],q[h][2dp+1]) (*) (rpr[j][2dp],rpr[j][2dp+1])
// qs pre-packed [dp][h][e] so 2 uniform LDS.128 serve 4 heads per dp; NO dup2.
// Thread = (head-group g = t>>7, jloc = t&127); chunk 128 j, double-buffered
// cp16 pipeline, 2 CTAs/SM. Logits in regs; block softmax; coalesced writes.
// ---------------------------------------------------------------------------
static constexpr int K2_CHUNK = 128;
static constexpr int K2_PITCH = 68;                      // 16B-aligned rows
static constexpr int K2_BUF = K2_CHUNK * K2_PITCH;       // 8704 floats
static constexpr int K2_SMEM = (576 + 2 * K2_BUF) * 4;   // 71936 B

__device__ __forceinline__ void k2_stage(uint32_t rs_u, const float* __restrict__ src,
                                         int t)
{
    // 128 rows x 16 float4 = 2048 cp16; 8 per thread, coalesced
    #pragma unroll
    for (int m = 0; m < 8; m++) {
        const int idx = m * 256 + t;
        const int row = idx >> 4;
        const int gg  = idx & 15;
        cp16(rs_u + (uint32_t)(row * K2_PITCH + 4 * gg) * 4u, src + (size_t)idx * 4);
    }
    CP_COMMIT();
}

__global__ void __launch_bounds__(256, 2) k2_rpr_softmax(
    const float* __restrict__ q,
    const float* __restrict__ rpr,
    const int* __restrict__ mask,
    float* __restrict__ attn)
{
    extern __shared__ float sm2[];
    float* qs3   = sm2;             // [32 dp][8 h][2 e] = 512
    float* redmx = sm2 + 512;       // [8 h][4 warps]
    float* redsm = sm2 + 544;       // [8 h][4 warps]
    float* rs0   = sm2 + 576;       // [128][68]
    float* rs1   = rs0 + K2_BUF;

    const int b = blockIdx.y;
    const int i = blockIdx.x;
    const int t = threadIdx.x;
    const int g = t >> 7;           // head group: heads g*4 .. g*4+3
    const int hb = g * 4;
    const int jl = t & 127;
    const int w = t >> 5, lane = t & 31;

    const float* rbase = rpr + ((size_t)b * S_ + i) * S_ * DK_;
    const int* mrow = mask + ((size_t)b * S_ + i) * S_;
    const uint32_t ru[2] = { s2u(rs0), s2u(rs1) };
    const float* rp2[2] = { rs0, rs1 };

    k2_stage(ru[0], rbase, t);      // chunk 0 in flight first

    // qs3[dp][h][e] = q[b,h,i,2dp+e]/T  (overlaps the first stage)
    #pragma unroll
    for (int idx = t; idx < 512; idx += 256) {
        const int e = idx & 1, h = (idx >> 1) & 7, dp = idx >> 4;
        qs3[idx] = q[(((size_t)b * H_ + h) * S_ + i) * DK_ + 2 * dp + e] * INV_T;
    }

    float l[4][8];                  // [head-in-group][chunk]

    #pragma unroll
    for (int c = 0; c < 8; c++) {
        if (c) __syncthreads();     // prior readers of buf[(c+1)&1] done

        const int j = c * K2_CHUNK + jl;
        if (c < 7) {
            k2_stage(ru[(c + 1) & 1], rbase + (size_t)(c + 1) * K2_CHUNK * DK_, t);
        }

        const int mk = mrow[j];
        float a1v[4];               // attn1 prefetch for this thread's 4 heads
        #pragma unroll
        for (int hh = 0; hh < 4; hh++)
            a1v[hh] = attn[(((size_t)b * H_ + hb + hh) * S_ + i) * S_ + j];

        if (c < 7) { CP_WAIT1(); } else { CP_WAIT0(); }
        __syncthreads();

        unsigned long long acc[4] = {};      // per head, packed (even-d, odd-d)
        const float* rr = rp2[c & 1] + jl * K2_PITCH;
        #pragma unroll
        for (int gg = 0; gg < 16; gg++) {
            ulonglong2 rpv = *(const ulonglong2*)(rr + 4 * gg);  // dp=2gg, 2gg+1
            const float* qb0 = qs3 + (2 * gg) * 16 + hb * 2;
            ulonglong2 qA = *(const ulonglong2*)(qb0);           // dp0: h hb,hb+1
            ulonglong2 qB = *(const ulonglong2*)(qb0 + 4);       // dp0: h hb+2,hb+3
            ulonglong2 qC = *(const ulonglong2*)(qb0 + 16);      // dp1
            ulonglong2 qD = *(const ulonglong2*)(qb0 + 20);
            FMA2(acc[0], qA.x, rpv.x);
            FMA2(acc[1], qA.y, rpv.x);
            FMA2(acc[2], qB.x, rpv.x);
            FMA2(acc[3], qB.y, rpv.x);
            FMA2(acc[0], qC.x, rpv.y);
            FMA2(acc[1], qC.y, rpv.y);
            FMA2(acc[2], qD.x, rpv.y);
            FMA2(acc[3], qD.y, rpv.y);
        }
        #pragma unroll
        for (int hh = 0; hh < 4; hh++) {
            float2 pv = unpack2(acc[hh]);
            l[hh][c] = mk ? (pv.x + pv.y + a1v[hh]) : -1e9f;
        }
    }

    // ---- block softmax: head h lives on 4 warps (one head-group half) ----
    #pragma unroll
    for (int hh = 0; hh < 4; hh++) {
        float m = l[hh][0];
        #pragma unroll
        for (int c = 1; c < 8; c++) m = fmaxf(m, l[hh][c]);
        #pragma unroll
        for (int o = 16; o > 0; o >>= 1)
            m = fmaxf(m, __shfl_xor_sync(0xffffffffu, m, o));
        if (lane == 0) redmx[(hb + hh) * 4 + (w & 3)] = m;
    }
    __syncthreads();
    float mx[4];
    #pragma unroll
    for (int hh = 0; hh < 4; hh++) {
        const float* p = redmx + (hb + hh) * 4;
        mx[hh] = fmaxf(fmaxf(p[0], p[1]), fmaxf(p[2], p[3]));
    }
    #pragma unroll
    for (int hh = 0; hh < 4; hh++) {
        float s = 0.f;
        #pragma unroll
        for (int c = 0; c < 8; c++) {
            l[hh][c] = __expf(l[hh][c] - mx[hh]);
            s += l[hh][c];
        }
        #pragma unroll
        for (int o = 16; o > 0; o >>= 1)
            s += __shfl_xor_sync(0xffffffffu, s, o);
        if (lane == 0) redsm[(hb + hh) * 4 + (w & 3)] = s;
    }
    __syncthreads();
    #pragma unroll
    for (int hh = 0; hh < 4; hh++) {
        const float* p = redsm + (hb + hh) * 4;
        const float rinv = 1.0f / (p[0] + p[1] + p[2] + p[3]);
        float* arow = attn + (((size_t)b * H_ + hb + hh) * S_ + i) * S_;
        #pragma unroll
        for (int c = 0; c < 8; c++)
            arow[c * K2_CHUNK + jl] = l[hh][c] * rinv;
    }
}

// ---------------------------------------------------------------------------
// K3 (REBUILT): output[b,h,i,:] = sum_j attn[b,h,i,j] * v[b,h,j,:]
// j-parity packing: acc_i += (A[i][2jp],A[i][2jp+1]) (*) (V[2jp][n],V[2jp+1][n])
// A-pairs: warp-uniform LDS.128 (2 packed ops/load). V-pairs: 2 LDS.32 + pack,
// amortized over 8 i-rows. 32-row tiles, 4 CTAs/SM, double-buffered cp16.
// ---------------------------------------------------------------------------
static constexpr int K3_AS = 32 * 64;                    // 2048 floats
static constexpr int K3_VS = 64 * 64;                    // 4096 floats
static constexpr int K3_SMEM = 2 * (K3_AS + K3_VS) * 4;  // 49152 B

__device__ __forceinline__ void k3_stage(uint32_t as_u, uint32_t vs_u,
                                         const float* __restrict__ ab,
                                         const float* __restrict__ vb,
                                         int jc, int t)
{
    #pragma unroll
    for (int m = 0; m < 2; m++) {
        const int idx = m * 256 + t;
        const int row = idx >> 4;
        const int d4  = (idx & 15) << 2;
        cp16(as_u + (uint32_t)(row * 64 + d4) * 4u, ab + (size_t)row * S_ + jc + d4);
    }
    #pragma unroll
    for (int m = 0; m < 4; m++) {
        const int idx = m * 256 + t;
        const int row = idx >> 4;
        const int d4  = (idx & 15) << 2;
        cp16(vs_u + (uint32_t)(row * 64 + d4) * 4u, vb + (size_t)(jc + row) * DV_ + d4);
    }
    CP_COMMIT();
}

__global__ void __launch_bounds__(256, 4) k3_av(const float* __restrict__ attn,
                                                const float* __restrict__ v,
                                                float* __restrict__ out)
{
    extern __shared__ float sm3[];
    float* Asb[2] = { sm3,                    sm3 + (K3_AS + K3_VS) };
    float* Vsb[2] = { sm3 + K3_AS,            sm3 + (K3_AS + K3_VS) + K3_AS };

    const int bh = blockIdx.y;
    const int i0 = blockIdx.x * 32;
    const int t = threadIdx.x;
    const int iblk = t >> 6;     // 0..3 -> rows iblk*8 .. +7
    const int n = t & 63;
    const float* ab = attn + ((size_t)bh * S_ + i0) * S_;
    const float* vb = v + (size_t)bh * S_ * DV_;
    const uint32_t as_u[2] = { s2u(Asb[0]), s2u(Asb[1]) };
    const uint32_t vs_u[2] = { s2u(Vsb[0]), s2u(Vsb[1]) };

    unsigned long long acc[8] = {};   // 8 i-rows, packed (even-j, odd-j)

    k3_stage(as_u[0], vs_u[0], ab, vb, 0, t);

    for (int c = 0; c < 16; c++) {
        if (c < 15) {
            k3_stage(as_u[(c + 1) & 1], vs_u[(c + 1) & 1], ab, vb, (c + 1) * 64, t);
            CP_WAIT1();
        } else {
            CP_WAIT0();
        }
        __syncthreads();

        const float* As = Asb[c & 1] + iblk * 8 * 64;
        const float* Vs = Vsb[c & 1];
        #pragma unroll 4
        for (int jp2 = 0; jp2 < 16; jp2++) {
            const float* vc = Vs + (4 * jp2) * 64 + n;
            unsigned long long vp0 = pack2(vc[0],   vc[64]);
            unsigned long long vp1 = pack2(vc[128], vc[192]);
            #pragma unroll
            for (int r = 0; r < 8; r++) {
                ulonglong2 ap = *(const ulonglong2*)(As + r * 64 + 4 * jp2);
                FMA2(acc[r], ap.x, vp0);
                FMA2(acc[r], ap.y, vp1);
            }
        }
        __syncthreads();
    }

    float* ob = out + ((size_t)bh * S_ + i0 + iblk * 8) * DV_ + n;
    #pragma unroll
    for (int r = 0; r < 8; r++) {
        float2 pv = unpack2(acc[r]);
        ob[(size_t)r * DV_] = pv.x + pv.y;
    }
}

// ---------------------------------------------------------------------------
extern "C" void kernel_launch(void* const* d_in, const int* in_sizes, int n_in,
                              void* d_out, int out_size)
{
    const float* q    = (const float*)d_in[0];
    const float* k    = (const float*)d_in[1];
    const float* v    = (const float*)d_in[2];
    const int*   mask = (const int*)d_in[3];
    const float* rpr  = (const float*)d_in[4];
    float* out  = (float*)d_out;
    float* attn = out + OUT_ATTN_OFF;

    cudaFuncSetAttribute(k1_qk, cudaFuncAttributeMaxDynamicSharedMemorySize, K1_SMEM);
    cudaFuncSetAttribute(k2_rpr_softmax, cudaFuncAttributeMaxDynamicSharedMemorySize,
                         K2_SMEM);
    cudaFuncSetAttribute(k3_av, cudaFuncAttributeMaxDynamicSharedMemorySize, K3_SMEM);

    {   // K1: attn1 logits into attn region (scratch, rewritten by K2)
        dim3 grid(S_ / 64, S_ / 128, B_ * H_);
        k1_qk<<<grid, 256, K1_SMEM>>>(q, k, attn);
    }
    {   // K2: + positional term, mask, softmax
        dim3 grid(S_, B_);
        k2_rpr_softmax<<<grid, 256, K2_SMEM>>>(q, rpr, mask, attn);
    }
    {   // K3: output = attn @ v
        dim3 grid(S_ / 32, B_ * H_);
        k3_av<<<grid, 256, K3_SMEM>>>(attn, v, out);
    }
}